// round 1
// baseline (speedup 1.0000x reference)
#include <cuda_runtime.h>

// LSTM: B=2048, T=512, LATENT=18, HID=32, gates 4H=128.
// One warp processes 4 batch elements. Lane owns gates (i,f,g,o) for hidden
// index = lane. Packed f32x2 FMAs: accA=(i,f), accB=(g,o) per element.
// Weights in shared, pre-paired as ulonglong2 so LDS.128 gives both packed
// weight operands; h/z stored duplicated (v,v) so broadcast operand is free.

#define NB   2048
#define NT   512
#define NL   18
#define NH   32

typedef unsigned long long u64;

__device__ __forceinline__ u64 pk(float x, float y) {
    u64 r; asm("mov.b64 %0,{%1,%2};" : "=l"(r) : "f"(x), "f"(y)); return r;
}
__device__ __forceinline__ void upk(u64 v, float& x, float& y) {
    asm("mov.b64 {%0,%1},%2;" : "=f"(x), "=f"(y) : "l"(v));
}
__device__ __forceinline__ u64 ffma2(u64 a, u64 b, u64 c) {
    u64 d; asm("fma.rn.f32x2 %0,%1,%2,%3;" : "=l"(d) : "l"(a), "l"(b), "l"(c));
    return d;
}

__device__ __forceinline__ float sigmoid_fast(float x) {
    return __fdividef(1.0f, 1.0f + __expf(-x));
}
__device__ __forceinline__ float tanh_fast(float x) {
    // 1 - 2/(e^{2x}+1); exact limits at +/-inf, ~2-ulp accuracy via __expf.
    return 1.0f - __fdividef(2.0f, __expf(2.0f * x) + 1.0f);
}

__global__ __launch_bounds__(128, 1)
void lstm_dyn_kernel(const float* __restrict__ z,
                     const float* __restrict__ Wih,
                     const float* __restrict__ Whh,
                     const float* __restrict__ bih,
                     const float* __restrict__ bhh,
                     const float* __restrict__ Wout,
                     const float* __restrict__ bout,
                     float* __restrict__ out)
{
    // Weight tiles, shared per block (same for all warps).
    __shared__ ulonglong2 sWih[NL][32];   // [d][lane] = paired ((Wi,Wf),(Wg,Wo)) col d
    __shared__ ulonglong2 sWhh[NH][32];   // [j][lane]
    __shared__ u64        sWoutD[NH][NL]; // [j][m] = (w,w) duplicated
    __shared__ float      sBias[128];     // b_ih + b_hh
    // Per-warp state rings (duplicated / pair-packed h and z).
    __shared__ u64 sHdup[4][4][NH];       // [warp][elem][j] = (h,h)
    __shared__ u64 sHpair[4][2][NH];      // [warp][pair][j] = (h_e0,h_e1)
    __shared__ u64 sZdup[4][4][NL];       // [warp][elem][d] = (z,z)

    const int tid = threadIdx.x;

    // ---- one-time weight staging ----
    sBias[tid] = bih[tid] + bhh[tid];
    for (int idx = tid; idx < NL * 32; idx += 128) {
        int d = idx >> 5, l = idx & 31;
        sWih[d][l] = make_ulonglong2(
            pk(Wih[l * NL + d],        Wih[(32 + l) * NL + d]),
            pk(Wih[(64 + l) * NL + d], Wih[(96 + l) * NL + d]));
    }
    for (int idx = tid; idx < NH * 32; idx += 128) {
        int j = idx >> 5, l = idx & 31;
        sWhh[j][l] = make_ulonglong2(
            pk(Whh[l * NH + j],        Whh[(32 + l) * NH + j]),
            pk(Whh[(64 + l) * NH + j], Whh[(96 + l) * NH + j]));
    }
    for (int idx = tid; idx < NH * NL; idx += 128) {
        int j = idx / NL, m = idx % NL;
        float w = Wout[m * NH + j];
        sWoutD[j][m] = pk(w, w);
    }
    __syncthreads();

    const int warp = tid >> 5;
    const int lane = tid & 31;
    const int be = blockIdx.x * 16 + warp * 4;   // first of 4 batch elements

    // h = c = 0 initial state
    #pragma unroll
    for (int e = 0; e < 4; e++) sHdup[warp][e][lane] = 0ull;
    sHpair[warp][0][lane] = 0ull;
    sHpair[warp][1][lane] = 0ull;

    const u64 biasA = pk(sBias[lane],      sBias[32 + lane]);
    const u64 biasB = pk(sBias[64 + lane], sBias[96 + lane]);
    u64 biasO = 0ull;
    if (lane < NL) { float b = bout[lane]; biasO = pk(b, b); }

    const float* zp = z   + (size_t)be * NT * NL + lane;
    float*       op = out + (size_t)be * NT * NL + lane;

    float zc[4];
    if (lane < NL) {
        #pragma unroll
        for (int e = 0; e < 4; e++) zc[e] = zp[(size_t)e * NT * NL];
    }
    float cS[4] = {0.f, 0.f, 0.f, 0.f};
    float hS[4] = {0.f, 0.f, 0.f, 0.f};
    __syncwarp();

    for (int t = 0; t < NT; t++) {
        // stage current z (duplicated) for broadcast use
        if (lane < NL) {
            #pragma unroll
            for (int e = 0; e < 4; e++) sZdup[warp][e][lane] = pk(zc[e], zc[e]);
        }
        __syncwarp();
        // prefetch next timestep's z while we compute this one
        if (lane < NL && t + 1 < NT) {
            #pragma unroll
            for (int e = 0; e < 4; e++)
                zc[e] = zp[(size_t)e * NT * NL + (t + 1) * NL];
        }

        u64 aA[4], aB[4];
        #pragma unroll
        for (int e = 0; e < 4; e++) { aA[e] = biasA; aB[e] = biasB; }

        // input contribution: gates += W_ih @ z_t
        #pragma unroll
        for (int d = 0; d < NL; d++) {
            ulonglong2 w = sWih[d][lane];
            #pragma unroll
            for (int e = 0; e < 4; e++) {
                u64 zv = sZdup[warp][e][d];
                aA[e] = ffma2(zv, w.x, aA[e]);
                aB[e] = ffma2(zv, w.y, aB[e]);
            }
        }
        // recurrent contribution: gates += W_hh @ h_{t-1}
        #pragma unroll
        for (int j = 0; j < NH; j++) {
            ulonglong2 w = sWhh[j][lane];
            #pragma unroll
            for (int e = 0; e < 4; e++) {
                u64 hv = sHdup[warp][e][j];
                aA[e] = ffma2(hv, w.x, aA[e]);
                aB[e] = ffma2(hv, w.y, aB[e]);
            }
        }
        __syncwarp();   // all lanes done reading sHdup before we overwrite it

        // pointwise gate nonlinearity + state update
        #pragma unroll
        for (int e = 0; e < 4; e++) {
            float gi, gf, gg, go;
            upk(aA[e], gi, gf);
            upk(aB[e], gg, go);
            float i = sigmoid_fast(gi);
            float f = sigmoid_fast(gf);
            float g = tanh_fast(gg);
            float o = sigmoid_fast(go);
            float c = f * cS[e] + i * g;
            cS[e] = c;
            float h = o * tanh_fast(c);
            hS[e] = h;
            sHdup[warp][e][lane] = pk(h, h);
        }
        sHpair[warp][0][lane] = pk(hS[0], hS[1]);
        sHpair[warp][1][lane] = pk(hS[2], hS[3]);
        __syncwarp();

        // output projection: z_pred = h @ W_out^T + b_out  (pairs packed in f32x2)
        if (lane < NL) {
            u64 o0 = biasO, o1 = biasO;
            #pragma unroll
            for (int j = 0; j < NH; j++) {
                u64 w = sWoutD[j][lane];
                o0 = ffma2(sHpair[warp][0][j], w, o0);
                o1 = ffma2(sHpair[warp][1][j], w, o1);
            }
            float p0, p1, p2, p3;
            upk(o0, p0, p1);
            upk(o1, p2, p3);
            op[(size_t)0 * NT * NL + t * NL] = p0;
            op[(size_t)1 * NT * NL + t * NL] = p1;
            op[(size_t)2 * NT * NL + t * NL] = p2;
            op[(size_t)3 * NT * NL + t * NL] = p3;
        }
        // next iteration's __syncwarp (after zdup writes) orders against
        // lanes still in the output loop
    }

    // final hidden/cell state: out layout = [z_pred | h_n | c_n]
    float* hOut = out + (size_t)NB * NT * NL;
    float* cOut = hOut + (size_t)NB * NH;
    #pragma unroll
    for (int e = 0; e < 4; e++) {
        hOut[(be + e) * NH + lane] = hS[e];
        cOut[(be + e) * NH + lane] = cS[e];
    }
}

extern "C" void kernel_launch(void* const* d_in, const int* in_sizes, int n_in,
                              void* d_out, int out_size)
{
    const float* z    = (const float*)d_in[0];
    const float* Wih  = (const float*)d_in[1];
    const float* Whh  = (const float*)d_in[2];
    const float* bih  = (const float*)d_in[3];
    const float* bhh  = (const float*)d_in[4];
    const float* Wout = (const float*)d_in[5];
    const float* bout = (const float*)d_in[6];
    float* out = (float*)d_out;

    lstm_dyn_kernel<<<NB / 16, 128>>>(z, Wih, Whh, bih, bhh, Wout, bout, out);
}